// round 14
// baseline (speedup 1.0000x reference)
#include <cuda_runtime.h>
#include <cuda_bf16.h>
#include <cstdint>

// out[b,o] = sigmoid( mean_i( x[b,i]*W[i,o] + bias[i,o] ) )
// Ones-trick: C = [x | 1s] @ [W ; bias]  (K=2048), so colsum(bias) is part of
// the GEMM. ONE kernel, no prep, no epilogue, no grid sync.
// 128 CTAs x 512 thr: half 0 = x@W (K 0..1023), half 1 = 1s@bias (K 0..1023,
// A-tile = static ones buffer, no A loads). Inline f32->bf16 conversion with
// depth-2 register pipeline over 3 smem stages; per-half named barriers.

#define BATCH   256
#define INDIM   1024
#define OUTDIM  1024

#define BM 32
#define BN 64
#define BK 64
#define NITH 16                  // 1024 / 64 per half

#define A_ST 72                  // bf16 units per row (144B, ldmatrix-safe)
#define B_ST 72
#define A_TILE_BYTES (BM * A_ST * 2)   // 4608
#define B_TILE_BYTES (BK * B_ST * 2)   // 9216

#define H0_OFF   0
#define H0_STAGE (A_TILE_BYTES + B_TILE_BYTES)   // 13824
#define H0_B     A_TILE_BYTES
#define H1A_OFF  (3 * H0_STAGE)                  // 41472 (static ones tile)
#define H1B_OFF  (H1A_OFF + A_TILE_BYTES)        // 46080
#define RED_OFF  (H1B_OFF + 3 * B_TILE_BYTES)    // 73728
#define SMEM_TOTAL (RED_OFF + 256 * 8 * 4)       // 81920

__device__ __forceinline__ uint32_t pack_bf2(float lo, float hi) {
    __nv_bfloat162 v = __floats2bfloat162_rn(lo, hi);
    return *reinterpret_cast<uint32_t*>(&v);
}
__device__ __forceinline__ uint4 pack8(float4 a, float4 b) {
    uint4 u;
    u.x = pack_bf2(a.x, a.y); u.y = pack_bf2(a.z, a.w);
    u.z = pack_bf2(b.x, b.y); u.w = pack_bf2(b.z, b.w);
    return u;
}
__device__ __forceinline__ void ldmatrix_x4(uint32_t* r, uint32_t addr) {
    asm volatile("ldmatrix.sync.aligned.m8n8.x4.shared.b16 {%0,%1,%2,%3}, [%4];"
                 : "=r"(r[0]), "=r"(r[1]), "=r"(r[2]), "=r"(r[3]) : "r"(addr));
}
__device__ __forceinline__ void ldmatrix_x4_trans(uint32_t* r, uint32_t addr) {
    asm volatile("ldmatrix.sync.aligned.m8n8.x4.trans.shared.b16 {%0,%1,%2,%3}, [%4];"
                 : "=r"(r[0]), "=r"(r[1]), "=r"(r[2]), "=r"(r[3]) : "r"(addr));
}
__device__ __forceinline__ void mma_bf16(float* c, const uint32_t* a, uint32_t b0, uint32_t b1) {
    asm volatile("mma.sync.aligned.m16n8k16.row.col.f32.bf16.bf16.f32 "
                 "{%0,%1,%2,%3}, {%4,%5,%6,%7}, {%8,%9}, {%0,%1,%2,%3};"
                 : "+f"(c[0]), "+f"(c[1]), "+f"(c[2]), "+f"(c[3])
                 : "r"(a[0]), "r"(a[1]), "r"(a[2]), "r"(a[3]), "r"(b0), "r"(b1));
}
__device__ __forceinline__ void bar_named(int id) {
    asm volatile("bar.sync %0, 256;" :: "r"(id) : "memory");
}
__device__ __forceinline__ float sigmoidf_(float t) {
    return 1.0f / (1.0f + __expf(-t));
}

// ---------------------------------------------------------------------------
__global__ void __launch_bounds__(512) fused_kernel(
        const float* __restrict__ x,
        const float* __restrict__ w,
        const float* __restrict__ bias,
        float* __restrict__ out) {
    extern __shared__ __align__(16) char smem[];

    const int tid  = threadIdx.x;
    const int half = tid >> 8;       // 0: x@W, 1: ones@bias
    const int htid = tid & 255;
    const int lane = tid & 31;
    const int wid  = htid >> 5;      // 0..7 within half
    const int wm   = wid >> 2;       // 0..1 -> 16 rows
    const int wn   = wid & 3;        // 0..3 -> 16 cols
    const int m0   = blockIdx.y * BM;
    const int n0   = blockIdx.x * BN;

    const uint32_t S = (uint32_t)__cvta_generic_to_shared(smem);

    // fragment byte offsets within a tile (A-local / B-local)
    const int lr = lane & 15;
    const int lc = (lane >> 4) << 3;
    uint32_t a_off[4], b_off[4];
    #pragma unroll
    for (int s = 0; s < 4; ++s) {
        a_off[s] = ((wm * 16 + lr) * A_ST + s * 16 + lc) * 2;
        b_off[s] = ((s * 16 + lr) * B_ST + wn * 16 + lc) * 2;
    }

    float acc[2][4];
    #pragma unroll
    for (int i = 0; i < 2; ++i)
        #pragma unroll
        for (int c = 0; c < 4; ++c)
            acc[i][c] = 0.0f;

    // B load mapping (both halves): row = k-within-tile, 16 f32 per thread
    const int b_row = htid >> 2;         // 0..63
    const int b_cg  = htid & 3;          // 0..3 -> cols b_cg*16..+15
    const float* gB = (half ? bias : w) + (size_t)b_row * OUTDIM + n0 + b_cg * 16;
    uint4* BsD;  // generic pointer for STS of B (2 x uint4)
    // A load mapping (half 0 only): row 0..31, 8 f32 per thread
    const int a_row = htid >> 3;         // 0..31
    const int a_cg  = htid & 7;          // 0..7 -> cols a_cg*8..+7
    const float* gA = x + (size_t)(m0 + a_row) * INDIM + a_cg * 8;

    float4 rB[2][4];
    float4 rA[2][2];

    if (half == 0) {
        // ---------------- half 0: x @ W ----------------
        // prologue: LDG k0, k1; STS k0; bar
        #pragma unroll
        for (int bnk = 0; bnk < 2; ++bnk) {
            const float* pa = gA + bnk * BK;
            rA[bnk][0] = *(const float4*)(pa);
            rA[bnk][1] = *(const float4*)(pa + 4);
            const float* pb = gB + (size_t)bnk * BK * OUTDIM;
            rB[bnk][0] = *(const float4*)(pb);
            rB[bnk][1] = *(const float4*)(pb + 4);
            rB[bnk][2] = *(const float4*)(pb + 8);
            rB[bnk][3] = *(const float4*)(pb + 12);
        }
        {   // STS stage 0 (k0 = bank 0)
            char* st = smem + H0_OFF;
            *reinterpret_cast<uint4*>(st + (a_row * A_ST + a_cg * 8) * 2) =
                pack8(rA[0][0], rA[0][1]);
            uint4* bd = reinterpret_cast<uint4*>(st + H0_B + (b_row * B_ST + b_cg * 16) * 2);
            bd[0] = pack8(rB[0][0], rB[0][1]);
            bd[1] = pack8(rB[0][2], rB[0][3]);
        }
        bar_named(1);

        for (int it = 0; it < NITH; ++it) {
            // LDG k(it+2) into bank it%2
            if (it + 2 < NITH) {
                const int bnk = it & 1;
                const float* pa = gA + (it + 2) * BK;
                rA[bnk][0] = *(const float4*)(pa);
                rA[bnk][1] = *(const float4*)(pa + 4);
                const float* pb = gB + (size_t)(it + 2) * BK * OUTDIM;
                rB[bnk][0] = *(const float4*)(pb);
                rB[bnk][1] = *(const float4*)(pb + 4);
                rB[bnk][2] = *(const float4*)(pb + 8);
                rB[bnk][3] = *(const float4*)(pb + 12);
            }
            // STS k(it+1) (bank (it+1)%2) into stage (it+1)%3
            if (it + 1 < NITH) {
                const int bnk = (it + 1) & 1;
                char* st = smem + H0_OFF + ((it + 1) % 3) * H0_STAGE;
                *reinterpret_cast<uint4*>(st + (a_row * A_ST + a_cg * 8) * 2) =
                    pack8(rA[bnk][0], rA[bnk][1]);
                uint4* bd = reinterpret_cast<uint4*>(st + H0_B + (b_row * B_ST + b_cg * 16) * 2);
                bd[0] = pack8(rB[bnk][0], rB[bnk][1]);
                bd[1] = pack8(rB[bnk][2], rB[bnk][3]);
            }
            bar_named(1);

            const uint32_t Ab = S + H0_OFF + (it % 3) * H0_STAGE;
            const uint32_t Bb = Ab + H0_B;
            #pragma unroll
            for (int s = 0; s < 4; ++s) {
                uint32_t af[4], bf[4];
                ldmatrix_x4(af, Ab + a_off[s]);
                ldmatrix_x4_trans(bf, Bb + b_off[s]);
                mma_bf16(acc[0], af, bf[0], bf[1]);
                mma_bf16(acc[1], af, bf[2], bf[3]);
            }
        }
    } else {
        // ---------------- half 1: ones @ bias ----------------
        // fill static ones A-tile (bf16 1.0 pairs), once
        {
            uint32_t* oa = reinterpret_cast<uint32_t*>(smem + H1A_OFF);
            for (int i = htid; i < A_TILE_BYTES / 4; i += 256)
                oa[i] = 0x3F803F80u;
        }
        // prologue: LDG k0,k1; STS k0; bar
        #pragma unroll
        for (int bnk = 0; bnk < 2; ++bnk) {
            const float* pb = gB + (size_t)bnk * BK * OUTDIM;
            rB[bnk][0] = *(const float4*)(pb);
            rB[bnk][1] = *(const float4*)(pb + 4);
            rB[bnk][2] = *(const float4*)(pb + 8);
            rB[bnk][3] = *(const float4*)(pb + 12);
        }
        {
            uint4* bd = reinterpret_cast<uint4*>(smem + H1B_OFF + (b_row * B_ST + b_cg * 16) * 2);
            bd[0] = pack8(rB[0][0], rB[0][1]);
            bd[1] = pack8(rB[0][2], rB[0][3]);
        }
        bar_named(2);

        const uint32_t Aones = S + H1A_OFF;
        for (int it = 0; it < NITH; ++it) {
            if (it + 2 < NITH) {
                const int bnk = it & 1;
                const float* pb = gB + (size_t)(it + 2) * BK * OUTDIM;
                rB[bnk][0] = *(const float4*)(pb);
                rB[bnk][1] = *(const float4*)(pb + 4);
                rB[bnk][2] = *(const float4*)(pb + 8);
                rB[bnk][3] = *(const float4*)(pb + 12);
            }
            if (it + 1 < NITH) {
                const int bnk = (it + 1) & 1;
                uint4* bd = reinterpret_cast<uint4*>(
                    smem + H1B_OFF + ((it + 1) % 3) * B_TILE_BYTES
                         + (b_row * B_ST + b_cg * 16) * 2);
                bd[0] = pack8(rB[bnk][0], rB[bnk][1]);
                bd[1] = pack8(rB[bnk][2], rB[bnk][3]);
            }
            bar_named(2);

            const uint32_t Bb = S + H1B_OFF + (it % 3) * B_TILE_BYTES;
            #pragma unroll
            for (int s = 0; s < 4; ++s) {
                uint32_t af[4], bf[4];
                ldmatrix_x4(af, Aones + a_off[s]);
                ldmatrix_x4_trans(bf, Bb + b_off[s]);
                mma_bf16(acc[0], af, bf[0], bf[1]);
                mma_bf16(acc[1], af, bf[2], bf[3]);
            }
        }
    }

    // ---- combine halves via smem ----
    float* red = reinterpret_cast<float*>(smem + RED_OFF);
    if (half == 1) {
        float4* r4 = reinterpret_cast<float4*>(&red[htid * 8]);
        r4[0] = make_float4(acc[0][0], acc[0][1], acc[0][2], acc[0][3]);
        r4[1] = make_float4(acc[1][0], acc[1][1], acc[1][2], acc[1][3]);
    }
    __syncthreads();

    if (half == 0) {
        const float4* r4 = reinterpret_cast<const float4*>(&red[htid * 8]);
        float4 p0 = r4[0], p1 = r4[1];
        acc[0][0] += p0.x; acc[0][1] += p0.y; acc[0][2] += p0.z; acc[0][3] += p0.w;
        acc[1][0] += p1.x; acc[1][1] += p1.y; acc[1][2] += p1.z; acc[1][3] += p1.w;

        const float inv = 1.0f / (float)INDIM;
        const int crow = lane >> 2;
        const int ccol = (lane & 3) << 1;
        #pragma unroll
        for (int nt = 0; nt < 2; ++nt) {
            const int col  = n0 + wn * 16 + nt * 8 + ccol;
            const int row0 = m0 + wm * 16 + crow;
            float2 r0 = make_float2(sigmoidf_(acc[nt][0] * inv),
                                    sigmoidf_(acc[nt][1] * inv));
            float2 r1 = make_float2(sigmoidf_(acc[nt][2] * inv),
                                    sigmoidf_(acc[nt][3] * inv));
            *reinterpret_cast<float2*>(&out[(size_t)row0 * OUTDIM + col])       = r0;
            *reinterpret_cast<float2*>(&out[(size_t)(row0 + 8) * OUTDIM + col]) = r1;
        }
    }
}

// ---------------------------------------------------------------------------
extern "C" void kernel_launch(void* const* d_in, const int* in_sizes, int n_in,
                              void* d_out, int out_size) {
    const float* x    = (const float*)d_in[0];
    const float* wgt  = (const float*)d_in[1];
    const float* bias = (const float*)d_in[2];
    float* out        = (float*)d_out;
    (void)in_sizes; (void)n_in; (void)out_size;

    cudaFuncSetAttribute(fused_kernel,
                         cudaFuncAttributeMaxDynamicSharedMemorySize, SMEM_TOTAL);

    dim3 g(OUTDIM / BN, BATCH / BM);   // (16, 8) = 128 CTAs
    fused_kernel<<<g, 512, SMEM_TOTAL>>>(x, wgt, bias, out);
}

// round 15
// speedup vs baseline: 1.2285x; 1.2285x over previous
#include <cuda_runtime.h>
#include <cuda_bf16.h>
#include <cstdint>

// out[b,o] = sigmoid( (x@W + colsum(bias))[b,o] / 1024 )
// R3 architecture (best: 14.9us) with two fixes:
//  - GEMM: depth-2 register prefetch over 3 smem stages, order
//    LDG(k+2) -> MMA(k) -> STS(k+1) -> sync  (full-iteration load lead)
//  - Epilogue: 128 CTAs, 2 float4/thread, all loads issued up front (__ldcg)

#define BATCH   256
#define INDIM   1024
#define OUTDIM  1024

#define KSPLIT  4
#define KCHUNK  (INDIM / KSPLIT)   // 256
#define BK      32
#define NIT     (KCHUNK / BK)      // 8
#define BM      64
#define BN      64

#define A_STRIDE 40   // bf16 units (80B rows, ldmatrix conflict-free)
#define B_STRIDE 72   // bf16 units (144B rows)

// scratch (device globals: no allocation allowed)
__device__ float g_part[KSPLIT][BATCH * OUTDIM];   // 4 MB fp32 partials
__device__ float g_bias_part[KSPLIT][OUTDIM];      // per-k-slice bias colsums

__device__ __forceinline__ void ldmatrix_x4(uint32_t* r, uint32_t addr) {
    asm volatile("ldmatrix.sync.aligned.m8n8.x4.shared.b16 {%0,%1,%2,%3}, [%4];"
                 : "=r"(r[0]), "=r"(r[1]), "=r"(r[2]), "=r"(r[3]) : "r"(addr));
}
__device__ __forceinline__ void ldmatrix_x4_trans(uint32_t* r, uint32_t addr) {
    asm volatile("ldmatrix.sync.aligned.m8n8.x4.trans.shared.b16 {%0,%1,%2,%3}, [%4];"
                 : "=r"(r[0]), "=r"(r[1]), "=r"(r[2]), "=r"(r[3]) : "r"(addr));
}
__device__ __forceinline__ void mma_bf16(float* c, const uint32_t* a, uint32_t b0, uint32_t b1) {
    asm volatile("mma.sync.aligned.m16n8k16.row.col.f32.bf16.bf16.f32 "
                 "{%0,%1,%2,%3}, {%4,%5,%6,%7}, {%8,%9}, {%0,%1,%2,%3};"
                 : "+f"(c[0]), "+f"(c[1]), "+f"(c[2]), "+f"(c[3])
                 : "r"(a[0]), "r"(a[1]), "r"(a[2]), "r"(a[3]), "r"(b0), "r"(b1));
}
__device__ __forceinline__ uint32_t pack_bf2(float lo, float hi) {
    __nv_bfloat162 v = __floats2bfloat162_rn(lo, hi);
    return *reinterpret_cast<uint32_t*>(&v);
}
__device__ __forceinline__ void pack_store16(__nv_bfloat16* dst, float4 a, float4 b) {
    uint4 u;
    u.x = pack_bf2(a.x, a.y); u.y = pack_bf2(a.z, a.w);
    u.z = pack_bf2(b.x, b.y); u.w = pack_bf2(b.z, b.w);
    *reinterpret_cast<uint4*>(dst) = u;
}
__device__ __forceinline__ float sigmoidf_(float t) {
    return 1.0f / (1.0f + __expf(-t));
}

// ---------------------------------------------------------------------------
// Kernel 1: split-K GEMM partials + bias colsum partials, one launch.
// grid = (16 n-tiles, 5, 4 k-slices); y<4 => GEMM m-tile, y==4 => bias block.
// ---------------------------------------------------------------------------
__global__ void __launch_bounds__(256) gemm_splitk_kernel(
        const float* __restrict__ x,
        const float* __restrict__ w,
        const float* __restrict__ bias) {
    __shared__ __nv_bfloat16 As[3][BM * A_STRIDE];
    __shared__ __nv_bfloat16 Bs[3][BK * B_STRIDE];
    __shared__ float red[4][BN];

    const int tid = threadIdx.x;
    const int n0  = blockIdx.x * BN;
    const int kz  = blockIdx.z;
    const int k0  = kz * KCHUNK;

    // ---------------- bias colsum blocks ----------------
    if (blockIdx.y == 4) {
        const int col = tid & 63;
        const int rg  = tid >> 6;            // 4 groups x 64 rows
        const float* bp = bias + (size_t)(k0 + rg * 64) * OUTDIM + n0 + col;
        float s = 0.0f;
        #pragma unroll 16
        for (int r = 0; r < 64; ++r)
            s += __ldg(bp + (size_t)r * OUTDIM);
        red[rg][col] = s;
        __syncthreads();
        if (tid < 64) {
            float t = red[0][tid] + red[1][tid] + red[2][tid] + red[3][tid];
            g_bias_part[kz][n0 + tid] = t;
        }
        return;
    }

    // ---------------- GEMM blocks ----------------
    const int m0   = blockIdx.y * BM;
    const int lane = tid & 31;
    const int wid  = tid >> 5;
    const int wm   = wid >> 2;   // 0..1 -> 32 rows
    const int wn   = wid & 3;    // 0..3 -> 16 cols

    const int arow = tid >> 2;           // 0..63
    const int ak   = (tid & 3) << 3;     // 0,8,16,24
    const int brow = tid >> 3;           // 0..31
    const int bno  = (tid & 7) << 3;     // 0..56

    const float* xg = x + (size_t)(m0 + arow) * INDIM + k0 + ak;
    const float* wg = w + (size_t)(k0 + brow) * OUTDIM + n0 + bno;

    float acc[2][2][4];
    #pragma unroll
    for (int i = 0; i < 2; ++i)
        #pragma unroll
        for (int j = 0; j < 2; ++j)
            #pragma unroll
            for (int c = 0; c < 4; ++c)
                acc[i][j][c] = 0.0f;

    const int lr = lane & 15;
    const int lc = (lane >> 4) << 3;
    uint32_t a_off[2][2], b_off[2];
    #pragma unroll
    for (int mt = 0; mt < 2; ++mt)
        #pragma unroll
        for (int s = 0; s < 2; ++s)
            a_off[mt][s] = ((wm * 32 + mt * 16 + lr) * A_STRIDE + s * 16 + lc) * 2;
    #pragma unroll
    for (int s = 0; s < 2; ++s)
        b_off[s] = ((s * 16 + lr) * B_STRIDE + wn * 16 + lc) * 2;

    const uint32_t As_base = (uint32_t)__cvta_generic_to_shared(&As[0][0]);
    const uint32_t Bs_base = (uint32_t)__cvta_generic_to_shared(&Bs[0][0]);
    const uint32_t A_STG = BM * A_STRIDE * 2;   // bytes per A stage
    const uint32_t B_STG = BK * B_STRIDE * 2;   // bytes per B stage

    // ---- depth-2 register prefetch: banks 0,1 hold k-chunks it+? ----
    float4 aR[2][2], bR[2][2];

    // prologue: LDG k0 -> bank0, k1 -> bank1; STS bank0 -> stage0; sync
    #pragma unroll
    for (int bnk = 0; bnk < 2; ++bnk) {
        const float* pa = xg + bnk * BK;
        aR[bnk][0] = *(const float4*)(pa);
        aR[bnk][1] = *(const float4*)(pa + 4);
        const float* pb = wg + (size_t)bnk * BK * OUTDIM;
        bR[bnk][0] = *(const float4*)(pb);
        bR[bnk][1] = *(const float4*)(pb + 4);
    }
    pack_store16(&As[0][arow * A_STRIDE + ak], aR[0][0], aR[0][1]);
    pack_store16(&Bs[0][brow * B_STRIDE + bno], bR[0][0], bR[0][1]);
    __syncthreads();

    #pragma unroll
    for (int it = 0; it < NIT; ++it) {
        // 1) LDG k(it+2) into bank it&1 (replaces consumed k(it))
        if (it + 2 < NIT) {
            const int bnk = it & 1;
            const float* pa = xg + (it + 2) * BK;
            aR[bnk][0] = *(const float4*)(pa);
            aR[bnk][1] = *(const float4*)(pa + 4);
            const float* pb = wg + (size_t)(it + 2) * BK * OUTDIM;
            bR[bnk][0] = *(const float4*)(pb);
            bR[bnk][1] = *(const float4*)(pb + 4);
        }

        // 2) MMA on stage it%3 (data stored at iter it-1, synced)
        const uint32_t Ab = As_base + (it % 3) * A_STG;
        const uint32_t Bb = Bs_base + (it % 3) * B_STG;
        #pragma unroll
        for (int s = 0; s < 2; ++s) {
            uint32_t af[2][4], bf[4];
            ldmatrix_x4(af[0], Ab + a_off[0][s]);
            ldmatrix_x4(af[1], Ab + a_off[1][s]);
            ldmatrix_x4_trans(bf, Bb + b_off[s]);
            #pragma unroll
            for (int mt = 0; mt < 2; ++mt) {
                mma_bf16(acc[mt][0], af[mt], bf[0], bf[1]);
                mma_bf16(acc[mt][1], af[mt], bf[2], bf[3]);
            }
        }

        // 3) STS k(it+1) from bank (it+1)&1 into stage (it+1)%3
        //    (that stage's readers finished at iter it-2, before sync(it-2))
        if (it + 1 < NIT) {
            const int bnk = (it + 1) & 1;
            const int st  = (it + 1) % 3;
            pack_store16(&As[st][arow * A_STRIDE + ak], aR[bnk][0], aR[bnk][1]);
            pack_store16(&Bs[st][brow * B_STRIDE + bno], bR[bnk][0], bR[bnk][1]);
            __syncthreads();
        }
    }

    // write fp32 partials
    float* pg = g_part[kz];
    const int crow = lane >> 2;
    const int ccol = (lane & 3) << 1;
    #pragma unroll
    for (int nt = 0; nt < 2; ++nt) {
        const int col = n0 + wn * 16 + nt * 8 + ccol;
        #pragma unroll
        for (int mt = 0; mt < 2; ++mt) {
            const int row0 = m0 + wm * 32 + mt * 16 + crow;
            *reinterpret_cast<float2*>(&pg[(size_t)row0 * OUTDIM + col]) =
                make_float2(acc[mt][nt][0], acc[mt][nt][1]);
            *reinterpret_cast<float2*>(&pg[(size_t)(row0 + 8) * OUTDIM + col]) =
                make_float2(acc[mt][nt][2], acc[mt][nt][3]);
        }
    }
}

// ---------------------------------------------------------------------------
// Kernel 2: reduce partials + bias, mean, sigmoid.
// grid = 128 x 256 thr, 2 float4 outputs / thread; all loads issued up front.
// ---------------------------------------------------------------------------
__global__ void __launch_bounds__(256) epilogue_kernel(float* __restrict__ out) {
    const int tid = threadIdx.x;
    const int i0  = blockIdx.x * 512 + tid;        // float4 index, chunk 0
    const int i1  = i0 + 256;                      // float4 index, chunk 1

    // issue ALL partial loads first (8 independent float4 loads)
    float4 p[2][KSPLIT];
    #pragma unroll
    for (int k = 0; k < KSPLIT; ++k) {
        p[0][k] = __ldcg(reinterpret_cast<const float4*>(g_part[k]) + i0);
        p[1][k] = __ldcg(reinterpret_cast<const float4*>(g_part[k]) + i1);
    }
    const int o0 = (i0 * 4) & (OUTDIM - 1);
    const int o1 = (i1 * 4) & (OUTDIM - 1);
    float4 bb[2][KSPLIT];
    #pragma unroll
    for (int k = 0; k < KSPLIT; ++k) {
        bb[0][k] = __ldcg(reinterpret_cast<const float4*>(&g_bias_part[k][o0]));
        bb[1][k] = __ldcg(reinterpret_cast<const float4*>(&g_bias_part[k][o1]));
    }

    const float inv = 1.0f / (float)INDIM;
    #pragma unroll
    for (int j = 0; j < 2; ++j) {
        float4 s = make_float4(0.f, 0.f, 0.f, 0.f);
        float4 b = make_float4(0.f, 0.f, 0.f, 0.f);
        #pragma unroll
        for (int k = 0; k < KSPLIT; ++k) {
            s.x += p[j][k].x; s.y += p[j][k].y; s.z += p[j][k].z; s.w += p[j][k].w;
            b.x += bb[j][k].x; b.y += bb[j][k].y; b.z += bb[j][k].z; b.w += bb[j][k].w;
        }
        float4 r;
        r.x = sigmoidf_((s.x + b.x) * inv);
        r.y = sigmoidf_((s.y + b.y) * inv);
        r.z = sigmoidf_((s.z + b.z) * inv);
        r.w = sigmoidf_((s.w + b.w) * inv);
        reinterpret_cast<float4*>(out)[j ? i1 : i0] = r;
    }
}

// ---------------------------------------------------------------------------
extern "C" void kernel_launch(void* const* d_in, const int* in_sizes, int n_in,
                              void* d_out, int out_size) {
    const float* x    = (const float*)d_in[0];
    const float* wgt  = (const float*)d_in[1];
    const float* bias = (const float*)d_in[2];
    float* out        = (float*)d_out;
    (void)in_sizes; (void)n_in; (void)out_size;

    dim3 g1(OUTDIM / BN, BATCH / BM + 1, KSPLIT);   // (16, 5, 4) = 320 CTAs
    gemm_splitk_kernel<<<g1, 256>>>(x, wgt, bias);

    epilogue_kernel<<<128, 256>>>(out);
}

// round 16
// speedup vs baseline: 1.4138x; 1.1509x over previous
#include <cuda_runtime.h>
#include <cuda_bf16.h>
#include <cstdint>

// out[b,o] = sigmoid( (x@W + colsum(bias))[b,o] / 1024 )
// R3 architecture (best measured: 14.9us) with ONE change: split-K partials
// are stored as bf16 (halves GEMM store + epilogue read traffic).
// Kernel 1: split-K(4) bf16 MMA GEMM + bias colsum CTAs (R3-exact mainloop).
// Kernel 2: reduce bf16 partials + bias, mean, sigmoid.

#define BATCH   256
#define INDIM   1024
#define OUTDIM  1024

#define KSPLIT  4
#define KCHUNK  (INDIM / KSPLIT)   // 256
#define BK      32
#define NIT     (KCHUNK / BK)      // 8
#define BM      64
#define BN      64

#define A_STRIDE 40   // bf16 units: 80B rows, ldmatrix conflict-free
#define B_STRIDE 72   // bf16 units: 144B rows
#define A_BUF_BYTES (BM * A_STRIDE * 2)
#define B_BUF_BYTES (BK * B_STRIDE * 2)

// scratch (device globals: no allocation allowed)
__device__ __nv_bfloat16 g_part[KSPLIT][BATCH * OUTDIM];   // 2 MB bf16 partials
__device__ float g_bias_part[KSPLIT][OUTDIM];              // per-slice bias colsums

__device__ __forceinline__ void ldmatrix_x4(uint32_t* r, uint32_t addr) {
    asm volatile("ldmatrix.sync.aligned.m8n8.x4.shared.b16 {%0,%1,%2,%3}, [%4];"
                 : "=r"(r[0]), "=r"(r[1]), "=r"(r[2]), "=r"(r[3]) : "r"(addr));
}
__device__ __forceinline__ void ldmatrix_x4_trans(uint32_t* r, uint32_t addr) {
    asm volatile("ldmatrix.sync.aligned.m8n8.x4.trans.shared.b16 {%0,%1,%2,%3}, [%4];"
                 : "=r"(r[0]), "=r"(r[1]), "=r"(r[2]), "=r"(r[3]) : "r"(addr));
}
__device__ __forceinline__ void mma_bf16(float* c, const uint32_t* a, uint32_t b0, uint32_t b1) {
    asm volatile("mma.sync.aligned.m16n8k16.row.col.f32.bf16.bf16.f32 "
                 "{%0,%1,%2,%3}, {%4,%5,%6,%7}, {%8,%9}, {%0,%1,%2,%3};"
                 : "+f"(c[0]), "+f"(c[1]), "+f"(c[2]), "+f"(c[3])
                 : "r"(a[0]), "r"(a[1]), "r"(a[2]), "r"(a[3]), "r"(b0), "r"(b1));
}
__device__ __forceinline__ uint32_t pack_bf2(float lo, float hi) {
    __nv_bfloat162 v = __floats2bfloat162_rn(lo, hi);
    return *reinterpret_cast<uint32_t*>(&v);
}
__device__ __forceinline__ void pack_store16(__nv_bfloat16* dst, float4 a, float4 b) {
    uint4 u;
    u.x = pack_bf2(a.x, a.y); u.y = pack_bf2(a.z, a.w);
    u.z = pack_bf2(b.x, b.y); u.w = pack_bf2(b.z, b.w);
    *reinterpret_cast<uint4*>(dst) = u;
}
__device__ __forceinline__ float sigmoidf_(float t) {
    return 1.0f / (1.0f + __expf(-t));
}

// ---------------------------------------------------------------------------
// Kernel 1: split-K GEMM partials (bf16) + bias colsum partials, one launch.
// grid = (16 n-tiles, 5, 4 k-slices); y<4 => GEMM m-tile, y==4 => bias block.
// Mainloop is byte-identical to the R3 best (2-stage, register prefetch).
// ---------------------------------------------------------------------------
__global__ void __launch_bounds__(256) gemm_splitk_kernel(
        const float* __restrict__ x,
        const float* __restrict__ w,
        const float* __restrict__ bias) {
    __shared__ __nv_bfloat16 As[2][BM * A_STRIDE];
    __shared__ __nv_bfloat16 Bs[2][BK * B_STRIDE];
    __shared__ float red[4][BN];

    const int tid = threadIdx.x;
    const int n0  = blockIdx.x * BN;
    const int kz  = blockIdx.z;
    const int k0  = kz * KCHUNK;

    // ---------------- bias colsum blocks ----------------
    if (blockIdx.y == 4) {
        const int col = tid & 63;
        const int rg  = tid >> 6;            // 4 groups x 64 rows
        const float* bp = bias + (size_t)(k0 + rg * 64) * OUTDIM + n0 + col;
        float s = 0.0f;
        #pragma unroll 16
        for (int r = 0; r < 64; ++r)
            s += __ldg(bp + (size_t)r * OUTDIM);
        red[rg][col] = s;
        __syncthreads();
        if (tid < 64) {
            float t = red[0][tid] + red[1][tid] + red[2][tid] + red[3][tid];
            g_bias_part[kz][n0 + tid] = t;
        }
        return;
    }

    // ---------------- GEMM blocks ----------------
    const int m0   = blockIdx.y * BM;
    const int lane = tid & 31;
    const int wid  = tid >> 5;
    const int wm   = wid >> 2;   // 0..1 -> 32 rows
    const int wn   = wid & 3;    // 0..3 -> 16 cols

    const int arow = tid >> 2;           // 0..63
    const int ak   = (tid & 3) << 3;     // 0,8,16,24
    const int brow = tid >> 3;           // 0..31
    const int bno  = (tid & 7) << 3;     // 0..56

    const float* xg = x + (size_t)(m0 + arow) * INDIM + k0 + ak;
    const float* wg = w + (size_t)(k0 + brow) * OUTDIM + n0 + bno;

    float acc[2][2][4];
    #pragma unroll
    for (int i = 0; i < 2; ++i)
        #pragma unroll
        for (int j = 0; j < 2; ++j)
            #pragma unroll
            for (int c = 0; c < 4; ++c)
                acc[i][j][c] = 0.0f;

    const int lr = lane & 15;
    const int lc = (lane >> 4) << 3;
    uint32_t a_off[2][2], b_off[2];
    #pragma unroll
    for (int mt = 0; mt < 2; ++mt)
        #pragma unroll
        for (int s = 0; s < 2; ++s)
            a_off[mt][s] = ((wm * 32 + mt * 16 + lr) * A_STRIDE + s * 16 + lc) * 2;
    #pragma unroll
    for (int s = 0; s < 2; ++s)
        b_off[s] = ((s * 16 + lr) * B_STRIDE + wn * 16 + lc) * 2;

    const uint32_t As_base = (uint32_t)__cvta_generic_to_shared(&As[0][0]);
    const uint32_t Bs_base = (uint32_t)__cvta_generic_to_shared(&Bs[0][0]);

    // prologue
    float4 aR0 = *(const float4*)(xg);
    float4 aR1 = *(const float4*)(xg + 4);
    float4 bR0 = *(const float4*)(wg);
    float4 bR1 = *(const float4*)(wg + 4);
    pack_store16(&As[0][arow * A_STRIDE + ak], aR0, aR1);
    pack_store16(&Bs[0][brow * B_STRIDE + bno], bR0, bR1);
    __syncthreads();

    #pragma unroll
    for (int it = 0; it < NIT; ++it) {
        const int buf = it & 1;

        if (it + 1 < NIT) {
            const int k1 = (it + 1) * BK;
            aR0 = *(const float4*)(xg + k1);
            aR1 = *(const float4*)(xg + k1 + 4);
            const float* wgk = wg + (size_t)k1 * OUTDIM;
            bR0 = *(const float4*)(wgk);
            bR1 = *(const float4*)(wgk + 4);
        }

        const uint32_t Ab = As_base + buf * A_BUF_BYTES;
        const uint32_t Bb = Bs_base + buf * B_BUF_BYTES;

        #pragma unroll
        for (int s = 0; s < 2; ++s) {
            uint32_t af[2][4], bf[4];
            ldmatrix_x4(af[0], Ab + a_off[0][s]);
            ldmatrix_x4(af[1], Ab + a_off[1][s]);
            ldmatrix_x4_trans(bf, Bb + b_off[s]);
            #pragma unroll
            for (int mt = 0; mt < 2; ++mt) {
                mma_bf16(acc[mt][0], af[mt], bf[0], bf[1]);
                mma_bf16(acc[mt][1], af[mt], bf[2], bf[3]);
            }
        }

        if (it + 1 < NIT) {
            const int nbuf = (it + 1) & 1;
            pack_store16(&As[nbuf][arow * A_STRIDE + ak], aR0, aR1);
            pack_store16(&Bs[nbuf][brow * B_STRIDE + bno], bR0, bR1);
            __syncthreads();
        }
    }

    // write bf16 partials (uint32 = 2 adjacent columns)
    __nv_bfloat16* pg = g_part[kz];
    const int crow = lane >> 2;
    const int ccol = (lane & 3) << 1;
    #pragma unroll
    for (int nt = 0; nt < 2; ++nt) {
        const int col = n0 + wn * 16 + nt * 8 + ccol;
        #pragma unroll
        for (int mt = 0; mt < 2; ++mt) {
            const int row0 = m0 + wm * 32 + mt * 16 + crow;
            *reinterpret_cast<uint32_t*>(&pg[(size_t)row0 * OUTDIM + col]) =
                pack_bf2(acc[mt][nt][0], acc[mt][nt][1]);
            *reinterpret_cast<uint32_t*>(&pg[(size_t)(row0 + 8) * OUTDIM + col]) =
                pack_bf2(acc[mt][nt][2], acc[mt][nt][3]);
        }
    }
}

// ---------------------------------------------------------------------------
// Kernel 2: reduce bf16 partials + bias, mean, sigmoid.
// grid = 256 x 256 thr, one float4 output per thread.
// ---------------------------------------------------------------------------
__global__ void __launch_bounds__(256) epilogue_kernel(float* __restrict__ out) {
    const int i4  = blockIdx.x * 256 + threadIdx.x;   // float4 index
    const int idx = i4 << 2;                          // element index
    const int o   = idx & (OUTDIM - 1);

    // partial loads: 4 independent uint2 (4 bf16 each), L2 via __ldcg
    uint2 pu[KSPLIT];
    #pragma unroll
    for (int k = 0; k < KSPLIT; ++k)
        pu[k] = __ldcg(reinterpret_cast<const uint2*>(&g_part[k][idx]));

    // bias loads: L1-cached (heavily shared lines)
    float4 bb[KSPLIT];
    #pragma unroll
    for (int k = 0; k < KSPLIT; ++k)
        bb[k] = __ldg(reinterpret_cast<const float4*>(&g_bias_part[k][o]));

    float4 s = make_float4(0.f, 0.f, 0.f, 0.f);
    #pragma unroll
    for (int k = 0; k < KSPLIT; ++k) {
        float2 lo = __bfloat1622float2(*reinterpret_cast<__nv_bfloat162*>(&pu[k].x));
        float2 hi = __bfloat1622float2(*reinterpret_cast<__nv_bfloat162*>(&pu[k].y));
        s.x += lo.x + bb[k].x;
        s.y += lo.y + bb[k].y;
        s.z += hi.x + bb[k].z;
        s.w += hi.y + bb[k].w;
    }

    const float inv = 1.0f / (float)INDIM;
    float4 r;
    r.x = sigmoidf_(s.x * inv);
    r.y = sigmoidf_(s.y * inv);
    r.z = sigmoidf_(s.z * inv);
    r.w = sigmoidf_(s.w * inv);
    reinterpret_cast<float4*>(out)[i4] = r;
}

// ---------------------------------------------------------------------------
extern "C" void kernel_launch(void* const* d_in, const int* in_sizes, int n_in,
                              void* d_out, int out_size) {
    const float* x    = (const float*)d_in[0];
    const float* wgt  = (const float*)d_in[1];
    const float* bias = (const float*)d_in[2];
    float* out        = (float*)d_out;
    (void)in_sizes; (void)n_in; (void)out_size;

    dim3 g1(OUTDIM / BN, BATCH / BM + 1, KSPLIT);   // (16, 5, 4) = 320 CTAs
    gemm_splitk_kernel<<<g1, 256>>>(x, wgt, bias);

    epilogue_kernel<<<256, 256>>>(out);
}